// round 2
// baseline (speedup 1.0000x reference)
#include <cuda_runtime.h>

#define E_MAX 100096
#define IN_F  256
#define HID   128

// scratch for t = X@W + b  (device globals are the allowed scratch mechanism)
__device__ float g_t[(size_t)E_MAX * HID];

// ---- packed f32x2 helpers (B300: FFMA2 doubles fp32 FMA rate; PTX-only) ----
__device__ __forceinline__ unsigned long long ffma2(unsigned long long a,
                                                    unsigned long long b,
                                                    unsigned long long c) {
    unsigned long long d;
    asm("fma.rn.f32x2 %0, %1, %2, %3;" : "=l"(d) : "l"(a), "l"(b), "l"(c));
    return d;
}
__device__ __forceinline__ unsigned long long dup2(float x) {
    unsigned long long d;
    unsigned u = __float_as_uint(x);
    asm("mov.b64 %0, {%1, %1};" : "=l"(d) : "r"(u));
    return d;
}

// =====================================================================
// Kernel 1: t = X @ W + b   (fp32, FFMA2, smem-tiled, TM=8 x TN=8)
// Block: 256 threads -> 128 rows x 128 cols tile. 8 k-chunks of 32.
// smem traffic = 1 B/FMA (balanced vs 128 B/cyc crossbar at 128 FMA/cyc/SM)
// =====================================================================
__global__ __launch_bounds__(256, 2)
void gemm_bias_kernel(const float* __restrict__ X,
                      const float* __restrict__ W,
                      const float* __restrict__ bias,
                      int E) {
    __shared__ float xs[128 * 33];   // [row][k], stride 33 -> conflict-free scalar STS/LDS
    __shared__ float ws[32 * 128];   // [k][h]

    const int tid  = threadIdx.x;
    const int tcol = tid & 15;       // 16 col groups x 8 cols
    const int trow = tid >> 4;       // 16 row groups x 8 rows
    const int rowBase = blockIdx.x * 128;

    unsigned long long acc[8][4];
#pragma unroll
    for (int r = 0; r < 8; ++r)
#pragma unroll
        for (int c = 0; c < 4; ++c) acc[r][c] = 0ull;

    const float4* X4  = (const float4*)X;   // row stride 64 float4
    const float4* W4  = (const float4*)W;   // row stride 32 float4
    float4*       ws4 = (float4*)ws;
    const ulonglong2* ws2 = (const ulonglong2*)ws;

    for (int kc = 0; kc < IN_F; kc += 32) {
        // stage X tile [128 rows][32 k]: 1024 float4, fully coalesced
#pragma unroll
        for (int i = 0; i < 4; ++i) {
            int idx = i * 256 + tid;
            int r = idx >> 3, f = idx & 7;
            int grow = rowBase + r;
            if (grow >= E) grow = E - 1;          // clamp (stores are guarded)
            float4 v = X4[grow * (IN_F / 4) + (kc >> 2) + f];
            xs[r * 33 + f * 4 + 0] = v.x;
            xs[r * 33 + f * 4 + 1] = v.y;
            xs[r * 33 + f * 4 + 2] = v.z;
            xs[r * 33 + f * 4 + 3] = v.w;
        }
        // stage W tile [32][128]: 1024 float4, coalesced
#pragma unroll
        for (int i = 0; i < 4; ++i) {
            int idx = i * 256 + tid;
            int kl = idx >> 5, h4 = idx & 31;
            ws4[kl * 32 + h4] = W4[(kc + kl) * 32 + h4];
        }
        __syncthreads();

#pragma unroll 4
        for (int k = 0; k < 32; ++k) {
            ulonglong2 wA = ws2[k * 32 + tcol * 2];       // w[c0..c3]
            ulonglong2 wB = ws2[k * 32 + tcol * 2 + 1];   // w[c4..c7]
#pragma unroll
            for (int r = 0; r < 8; ++r) {
                unsigned long long xd = dup2(xs[(trow * 8 + r) * 33 + k]);
                acc[r][0] = ffma2(xd, wA.x, acc[r][0]);
                acc[r][1] = ffma2(xd, wA.y, acc[r][1]);
                acc[r][2] = ffma2(xd, wB.x, acc[r][2]);
                acc[r][3] = ffma2(xd, wB.y, acc[r][3]);
            }
        }
        __syncthreads();
    }

    // epilogue: + bias, store fp32 t
    float bb[8];
#pragma unroll
    for (int c = 0; c < 8; ++c) bb[c] = bias[tcol * 8 + c];

    float4* T4 = (float4*)g_t;
#pragma unroll
    for (int r = 0; r < 8; ++r) {
        int grow = rowBase + trow * 8 + r;
        if (grow < E) {
            float4 o0, o1;
            o0.x = __uint_as_float((unsigned)(acc[r][0]))       + bb[0];
            o0.y = __uint_as_float((unsigned)(acc[r][0] >> 32)) + bb[1];
            o0.z = __uint_as_float((unsigned)(acc[r][1]))       + bb[2];
            o0.w = __uint_as_float((unsigned)(acc[r][1] >> 32)) + bb[3];
            o1.x = __uint_as_float((unsigned)(acc[r][2]))       + bb[4];
            o1.y = __uint_as_float((unsigned)(acc[r][2] >> 32)) + bb[5];
            o1.z = __uint_as_float((unsigned)(acc[r][3]))       + bb[6];
            o1.w = __uint_as_float((unsigned)(acc[r][3] >> 32)) + bb[7];
            T4[grow * 32 + tcol * 2]     = o0;
            T4[grow * 32 + tcol * 2 + 1] = o1;
        }
    }
}

// =====================================================================
// Kernel 2: out[i] = t[i] + sum_k t[nbr[i][k]]
// One warp per edge; lane handles one float4 (row = 32 float4 = 512 B).
// 16 independent gather LDG.128 per lane -> MLP=16; t (51 MB) lives in L2.
// =====================================================================
__global__ __launch_bounds__(256)
void gather_sum_kernel(const int* __restrict__ nbr,
                       float* __restrict__ out,
                       int E) {
    int gtid = blockIdx.x * blockDim.x + threadIdx.x;
    int e    = gtid >> 5;
    int lane = threadIdx.x & 31;
    if (e >= E) return;

    const float4* T4 = (const float4*)g_t;

    int j = 0;
    if (lane < 16) j = nbr[e * 16 + lane];

    float4 acc = T4[e * 32 + lane];

    float4 v[16];
#pragma unroll
    for (int k = 0; k < 16; ++k) {
        int n = __shfl_sync(0xffffffffu, j, k);
        v[k] = T4[n * 32 + lane];
    }
#pragma unroll
    for (int k = 0; k < 16; ++k) {
        acc.x += v[k].x;
        acc.y += v[k].y;
        acc.z += v[k].z;
        acc.w += v[k].w;
    }
    ((float4*)out)[e * 32 + lane] = acc;
}

extern "C" void kernel_launch(void* const* d_in, const int* in_sizes, int n_in,
                              void* d_out, int out_size) {
    const float* X   = (const float*)d_in[0];   // edge_feats [E, 256]
    const int*   nbr = (const int*)  d_in[1];   // neighbors  [E, 16]
    const float* W   = (const float*)d_in[2];   // W          [256, 128]
    const float* b   = (const float*)d_in[3];   // b          [128]
    float* out = (float*)d_out;                 // [E, 128]

    int E = in_sizes[0] / IN_F;

    int gblocks = (E + 127) / 128;
    gemm_bias_kernel<<<gblocks, 256>>>(X, W, b, E);

    long long threads = (long long)E * 32;      // one warp per edge
    int blocks2 = (int)((threads + 255) / 256);
    gather_sum_kernel<<<blocks2, 256>>>(nbr, out, E);
}

// round 4
// speedup vs baseline: 1.7475x; 1.7475x over previous
#include <cuda_runtime.h>
#include <cuda_bf16.h>
#include <cstdint>

#define E_MAX 100096
#define IN_F  256
#define HID   128

// scratch (device globals = allowed scratch)
__device__ float g_t[(size_t)E_MAX * HID];
__device__ __nv_bfloat16 g_wt_hi[HID * IN_F];   // W transposed [n][k], hi part
__device__ __nv_bfloat16 g_wt_lo[HID * IN_F];   // lo part

__device__ __forceinline__ uint32_t smem_u32(const void* p) {
    uint32_t a;
    asm("{ .reg .u64 t; cvta.to.shared.u64 t, %1; cvt.u32.u64 %0, t; }" : "=r"(a) : "l"(p));
    return a;
}
__device__ __forceinline__ void ldsm_x4(uint32_t& r0, uint32_t& r1, uint32_t& r2,
                                        uint32_t& r3, uint32_t addr) {
    asm volatile("ldmatrix.sync.aligned.m8n8.x4.shared.b16 {%0,%1,%2,%3}, [%4];"
                 : "=r"(r0), "=r"(r1), "=r"(r2), "=r"(r3) : "r"(addr));
}
__device__ __forceinline__ void mma16816(float* c, uint32_t a0, uint32_t a1,
                                         uint32_t a2, uint32_t a3,
                                         uint32_t b0, uint32_t b1) {
    asm volatile(
        "mma.sync.aligned.m16n8k16.row.col.f32.bf16.bf16.f32 "
        "{%0,%1,%2,%3}, {%4,%5,%6,%7}, {%8,%9}, {%0,%1,%2,%3};"
        : "+f"(c[0]), "+f"(c[1]), "+f"(c[2]), "+f"(c[3])
        : "r"(a0), "r"(a1), "r"(a2), "r"(a3), "r"(b0), "r"(b1));
}

// =====================================================================
// W transpose + bf16 hi/lo split (one-shot tiny kernel)
// =====================================================================
__global__ void wconv_kernel(const float* __restrict__ W) {
    int i = blockIdx.x * 256 + threadIdx.x;
    if (i >= IN_F * HID) return;
    int k = i >> 7, n = i & 127;
    float v = W[i];
    __nv_bfloat16 h = __float2bfloat16(v);
    float lo = v - __bfloat162float(h);
    g_wt_hi[n * IN_F + k] = h;
    g_wt_lo[n * IN_F + k] = __float2bfloat16(lo);
}

// =====================================================================
// t = X @ W + b : bf16 3-term split on mma.sync (HMMA), fp32 accum
// CTA = 128 rows x 128 cols, 8 warps (4m x 2n), warp tile 32x64, BK=32
// =====================================================================
#define BK 32
#define STR 40          // smem row stride in bf16: 80 B (16B-aligned, conflict-free ldsm)

__global__ __launch_bounds__(256, 2)
void gemm_mma_kernel(const float* __restrict__ X,
                     const float* __restrict__ bias,
                     int E) {
    __shared__ __nv_bfloat16 sAh[128 * STR];
    __shared__ __nv_bfloat16 sAl[128 * STR];
    __shared__ __nv_bfloat16 sBh[128 * STR];
    __shared__ __nv_bfloat16 sBl[128 * STR];

    const int tid  = threadIdx.x;
    const int wid  = tid >> 5;
    const int lane = tid & 31;
    const int wm   = wid & 3;        // 4 warp-rows of 32
    const int wn   = wid >> 2;       // 2 warp-cols of 64
    const int rowBase = blockIdx.x * 128;

    float acc[2][8][4];
#pragma unroll
    for (int mi = 0; mi < 2; ++mi)
#pragma unroll
        for (int ni = 0; ni < 8; ++ni)
#pragma unroll
            for (int q = 0; q < 4; ++q) acc[mi][ni][q] = 0.f;

    const float4* X4  = (const float4*)X;
    const uint4*  bh4 = (const uint4*)g_wt_hi;   // 32 uint4 per n-row
    const uint4*  bl4 = (const uint4*)g_wt_lo;

    const uint32_t sAh_b = smem_u32(sAh);
    const uint32_t sAl_b = smem_u32(sAl);
    const uint32_t sBh_b = smem_u32(sBh);
    const uint32_t sBl_b = smem_u32(sBl);

    // ldmatrix lane geometry (x4: mats (r0-7,k0-7)(r8-15,k0-7)(r0-7,k8-15)(r8-15,k8-15))
    const int lrow = (lane & 7) + ((lane >> 3) & 1) * 8;
    const int lkof = ((lane >> 4) & 1) * 8;

    for (int kc = 0; kc < IN_F / BK; ++kc) {
        // ---- stage A: 128 x 32 fp32 -> bf16 hi/lo ----
#pragma unroll
        for (int it = 0; it < 4; ++it) {
            int i = it * 256 + tid;       // 1024 float4
            int r = i >> 3, f = i & 7;    // 8 float4 per row
            int grow = rowBase + r;
            if (grow >= E) grow = E - 1;
            float4 v = X4[grow * (IN_F / 4) + kc * 8 + f];
            __nv_bfloat16 h0 = __float2bfloat16(v.x);
            __nv_bfloat16 h1 = __float2bfloat16(v.y);
            __nv_bfloat16 h2 = __float2bfloat16(v.z);
            __nv_bfloat16 h3 = __float2bfloat16(v.w);
            __nv_bfloat16 l0 = __float2bfloat16(v.x - __bfloat162float(h0));
            __nv_bfloat16 l1 = __float2bfloat16(v.y - __bfloat162float(h1));
            __nv_bfloat16 l2 = __float2bfloat16(v.z - __bfloat162float(h2));
            __nv_bfloat16 l3 = __float2bfloat16(v.w - __bfloat162float(h3));
            uint2 hp, lp;
            hp.x = ((uint32_t)__bfloat16_as_ushort(h1) << 16) | __bfloat16_as_ushort(h0);
            hp.y = ((uint32_t)__bfloat16_as_ushort(h3) << 16) | __bfloat16_as_ushort(h2);
            lp.x = ((uint32_t)__bfloat16_as_ushort(l1) << 16) | __bfloat16_as_ushort(l0);
            lp.y = ((uint32_t)__bfloat16_as_ushort(l3) << 16) | __bfloat16_as_ushort(l2);
            *(uint2*)(sAh + r * STR + f * 4) = hp;
            *(uint2*)(sAl + r * STR + f * 4) = lp;
        }
        // ---- stage B: 128 n x 32 k, hi+lo (uint4 = 8 bf16; 80B rows are 16B-aligned) ----
#pragma unroll
        for (int it = 0; it < 2; ++it) {
            int i = it * 256 + tid;       // 512 uint4 per matrix
            int n = i >> 2, q = i & 3;    // 4 uint4 per row
            *(uint4*)(sBh + n * STR + q * 8) = bh4[n * 32 + kc * 4 + q];
            *(uint4*)(sBl + n * STR + q * 8) = bl4[n * 32 + kc * 4 + q];
        }
        __syncthreads();

        // ---- compute: 2 k16-steps per chunk ----
#pragma unroll
        for (int ks = 0; ks < 2; ++ks) {
            const int kk = ks * 16;
            uint32_t af[2][4], bf[4][4];

            // pass 0: Ah x Bh
#pragma unroll
            for (int mi = 0; mi < 2; ++mi)
                ldsm_x4(af[mi][0], af[mi][1], af[mi][2], af[mi][3],
                        sAh_b + ((wm * 32 + mi * 16 + lrow) * STR + kk + lkof) * 2);
#pragma unroll
            for (int bi = 0; bi < 4; ++bi)
                ldsm_x4(bf[bi][0], bf[bi][1], bf[bi][2], bf[bi][3],
                        sBh_b + ((wn * 64 + bi * 16 + lrow) * STR + kk + lkof) * 2);
#pragma unroll
            for (int mi = 0; mi < 2; ++mi)
#pragma unroll
                for (int bi = 0; bi < 4; ++bi) {
                    mma16816(acc[mi][bi * 2 + 0], af[mi][0], af[mi][1], af[mi][2], af[mi][3],
                             bf[bi][0], bf[bi][2]);
                    mma16816(acc[mi][bi * 2 + 1], af[mi][0], af[mi][1], af[mi][2], af[mi][3],
                             bf[bi][1], bf[bi][3]);
                }

            // pass 1: Al x Bh (B fragments still resident)
#pragma unroll
            for (int mi = 0; mi < 2; ++mi)
                ldsm_x4(af[mi][0], af[mi][1], af[mi][2], af[mi][3],
                        sAl_b + ((wm * 32 + mi * 16 + lrow) * STR + kk + lkof) * 2);
#pragma unroll
            for (int mi = 0; mi < 2; ++mi)
#pragma unroll
                for (int bi = 0; bi < 4; ++bi) {
                    mma16816(acc[mi][bi * 2 + 0], af[mi][0], af[mi][1], af[mi][2], af[mi][3],
                             bf[bi][0], bf[bi][2]);
                    mma16816(acc[mi][bi * 2 + 1], af[mi][0], af[mi][1], af[mi][2], af[mi][3],
                             bf[bi][1], bf[bi][3]);
                }

            // pass 2: Ah x Bl
#pragma unroll
            for (int mi = 0; mi < 2; ++mi)
                ldsm_x4(af[mi][0], af[mi][1], af[mi][2], af[mi][3],
                        sAh_b + ((wm * 32 + mi * 16 + lrow) * STR + kk + lkof) * 2);
#pragma unroll
            for (int bi = 0; bi < 4; ++bi)
                ldsm_x4(bf[bi][0], bf[bi][1], bf[bi][2], bf[bi][3],
                        sBl_b + ((wn * 64 + bi * 16 + lrow) * STR + kk + lkof) * 2);
#pragma unroll
            for (int mi = 0; mi < 2; ++mi)
#pragma unroll
                for (int bi = 0; bi < 4; ++bi) {
                    mma16816(acc[mi][bi * 2 + 0], af[mi][0], af[mi][1], af[mi][2], af[mi][3],
                             bf[bi][0], bf[bi][2]);
                    mma16816(acc[mi][bi * 2 + 1], af[mi][0], af[mi][1], af[mi][2], af[mi][3],
                             bf[bi][1], bf[bi][3]);
                }
        }
        __syncthreads();
    }

    // ---- epilogue: + bias, store t ----
    const int gid = lane >> 2;           // c-frag row within m16
    const int cid = (lane & 3) * 2;      // c-frag col within n8
#pragma unroll
    for (int mi = 0; mi < 2; ++mi) {
        int row0 = rowBase + wm * 32 + mi * 16 + gid;
#pragma unroll
        for (int ni = 0; ni < 8; ++ni) {
            int col = wn * 64 + ni * 8 + cid;
            float b0 = __ldg(bias + col), b1 = __ldg(bias + col + 1);
            if (row0 < E) {
                float2 o = {acc[mi][ni][0] + b0, acc[mi][ni][1] + b1};
                *(float2*)(g_t + (size_t)row0 * HID + col) = o;
            }
            if (row0 + 8 < E) {
                float2 o = {acc[mi][ni][2] + b0, acc[mi][ni][3] + b1};
                *(float2*)(g_t + (size_t)(row0 + 8) * HID + col) = o;
            }
        }
    }
}

// =====================================================================
// out[i] = t[i] + sum_k t[nbr[i][k]]   (46.6us, L2-bound — unchanged)
// =====================================================================
__global__ __launch_bounds__(256)
void gather_sum_kernel(const int* __restrict__ nbr,
                       float* __restrict__ out,
                       int E) {
    int gtid = blockIdx.x * blockDim.x + threadIdx.x;
    int e    = gtid >> 5;
    int lane = threadIdx.x & 31;
    if (e >= E) return;

    const float4* T4 = (const float4*)g_t;

    int j = 0;
    if (lane < 16) j = nbr[e * 16 + lane];

    float4 acc = T4[e * 32 + lane];

    float4 v[16];
#pragma unroll
    for (int k = 0; k < 16; ++k) {
        int n = __shfl_sync(0xffffffffu, j, k);
        v[k] = T4[n * 32 + lane];
    }
#pragma unroll
    for (int k = 0; k < 16; ++k) {
        acc.x += v[k].x;
        acc.y += v[k].y;
        acc.z += v[k].z;
        acc.w += v[k].w;
    }
    ((float4*)out)[e * 32 + lane] = acc;
}

extern "C" void kernel_launch(void* const* d_in, const int* in_sizes, int n_in,
                              void* d_out, int out_size) {
    const float* X   = (const float*)d_in[0];   // edge_feats [E, 256]
    const int*   nbr = (const int*)  d_in[1];   // neighbors  [E, 16]
    const float* W   = (const float*)d_in[2];   // W          [256, 128]
    const float* b   = (const float*)d_in[3];   // b          [128]
    float* out = (float*)d_out;                 // [E, 128]

    int E = in_sizes[0] / IN_F;

    wconv_kernel<<<(IN_F * HID + 255) / 256, 256>>>(W);

    int gblocks = (E + 127) / 128;
    gemm_mma_kernel<<<gblocks, 256>>>(X, b, E);

    long long threads = (long long)E * 32;      // one warp per edge
    int blocks2 = (int)((threads + 255) / 256);
    gather_sum_kernel<<<blocks2, 256>>>(nbr, out, E);
}